// round 7
// baseline (speedup 1.0000x reference)
#include <cuda_runtime.h>
#include <cuda_fp16.h>
#include <cstdint>

// Problem dims
#define B_ROWS 8192
#define KDIM   4096
#define NDIM   4096
#define CAPQ   492

// GEMM tiling (fp16 operands, fp32 accum)
#define BM 128
#define BN 256
#define BK 128                         // 128 halves = 256 B rows
#define MT (B_ROWS / BM)               // 64
#define NT (NDIM / BN)                 // 16
#define KT (KDIM / BK)                 // 32
#define A_BYTES (BM * BK * 2)          // 32768
#define B_BYTES (BN * BK * 2)          // 65536
#define STAGE_BYTES (A_BYTES + B_BYTES)     // 98304
#define SMEM_SIZE (2 * STAGE_BYTES)         // 196608 -> 1 CTA/SM, 16 warps

// Scratch (allocations forbidden -> __device__ globals)
__device__ __half g_Wh[(size_t)NDIM * KDIM];   // half W, [n][k]
__device__ __half g_xh[(size_t)B_ROWS * KDIM]; // half x, [m][k]

// 256B-row swizzle: XOR 16B-chunk index within each 128B half by (row & 7)
__device__ __forceinline__ uint32_t swz(int r, int c16) {
    return (uint32_t)(r * 256 + ((((c16 & 7) ^ (r & 7)) + (c16 & 8)) << 4));
}

// -------------------------------------------------------------- pre-kernels --
__global__ __launch_bounds__(256)
void build_w_kernel(const float* __restrict__ values, const int* __restrict__ col) {
    __shared__ float row[KDIM];
    const int o   = blockIdx.x;
    const int tid = threadIdx.x;

    float4* r4 = (float4*)row;
    #pragma unroll
    for (int i = 0; i < KDIM / 4 / 256; i++)
        r4[i * 256 + tid] = make_float4(0.f, 0.f, 0.f, 0.f);
    __syncthreads();

    const float* v = values + (size_t)o * CAPQ;
    const int*   c = col    + (size_t)o * CAPQ;
    for (int s = tid; s < CAPQ; s += 256) {
        float val = v[s];
        if (val != 0.0f) atomicAdd(&row[c[s]], val);
    }
    __syncthreads();

    __half2* out = (__half2*)(g_Wh + (size_t)o * KDIM);
    #pragma unroll
    for (int i = 0; i < KDIM / 4 / 256; i++) {
        float4 f = r4[i * 256 + tid];
        int j = (i * 256 + tid) * 2;
        out[j]     = __floats2half2_rn(f.x, f.y);
        out[j + 1] = __floats2half2_rn(f.z, f.w);
    }
}

__global__ void cvt_x_kernel(const float4* __restrict__ x) {
    const size_t n4 = (size_t)B_ROWS * KDIM / 4;
    __half2* out = (__half2*)g_xh;
    for (size_t i = (size_t)blockIdx.x * blockDim.x + threadIdx.x; i < n4;
         i += (size_t)gridDim.x * blockDim.x) {
        float4 v = x[i];
        out[i * 2]     = __floats2half2_rn(v.x, v.y);
        out[i * 2 + 1] = __floats2half2_rn(v.z, v.w);
    }
}

// --------------------------------------------------------------- GEMM kernel -
// 512 threads = 16 warps in 2(M) x 8(N); warp tile 64x32; mma.m16n8k16 f16->f32.
// BK=128 halves -> 32 sync points; 2-stage cp.async pipeline (load of stage
// kt+1 overlaps compute of kt). 192KB smem, 1 CTA/SM, 16 warps/SM.
__global__ __launch_bounds__(512, 1)
void gemm_kernel(const float* __restrict__ bias, float* __restrict__ y)
{
    extern __shared__ __align__(128) unsigned char smem[];
    const uint32_t sbase = (uint32_t)__cvta_generic_to_shared(smem);
    const int tid  = threadIdx.x;
    const int lane = tid & 31;
    const int wid  = tid >> 5;
    const int wm   = wid & 1;      // 2 M groups of 64
    const int wn   = wid >> 1;     // 8 N groups of 32

    const int m0 = (blockIdx.x / NT) * BM;
    const int n0 = (blockIdx.x % NT) * BN;

    const __half* Ag = g_xh + (size_t)m0 * KDIM;
    const __half* Bg = g_Wh + (size_t)n0 * KDIM;

    auto load_stage = [&](int kt, int slot) {
        const uint32_t sa = sbase + slot * STAGE_BYTES;
        const uint32_t sb = sa + A_BYTES;
        const __half* ga = Ag + kt * BK;
        const __half* gb = Bg + kt * BK;
        #pragma unroll
        for (int i = 0; i < 4; i++) {            // A: 2048 16B chunks / 512 thr
            int chunk = i * 512 + tid;
            int r = chunk >> 4, c = chunk & 15;
            uint32_t so = sa + swz(r, c);
            const __half* g = ga + (size_t)r * KDIM + c * 8;
            asm volatile("cp.async.cg.shared.global [%0], [%1], 16;" :: "r"(so), "l"(g));
        }
        #pragma unroll
        for (int i = 0; i < 8; i++) {            // B: 4096 16B chunks
            int chunk = i * 512 + tid;
            int r = chunk >> 4, c = chunk & 15;
            uint32_t so = sb + swz(r, c);
            const __half* g = gb + (size_t)r * KDIM + c * 8;
            asm volatile("cp.async.cg.shared.global [%0], [%1], 16;" :: "r"(so), "l"(g));
        }
        asm volatile("cp.async.commit_group;" ::: "memory");
    };

    float acc[4][4][4];
    #pragma unroll
    for (int i = 0; i < 4; i++)
        #pragma unroll
        for (int j = 0; j < 4; j++)
            #pragma unroll
            for (int k = 0; k < 4; k++) acc[i][j][k] = 0.f;

    const int br_base = wn * 32 + ((lane >> 4) << 3) + (lane & 7);   // + q*16
    const int bc_sel  = (lane >> 3) & 1;                             // + 2*ks
    const int ar_base = wm * 64 + (lane & 15);                       // + mt*16
    const int ac_sel  = lane >> 4;                                   // + 2*ks

    auto compute_stage = [&](int slot) {
        const uint32_t sa = sbase + slot * STAGE_BYTES;
        const uint32_t sb = sa + A_BYTES;

        uint32_t bf[2][8];
        uint32_t af[2][4];

        auto ldB = [&](int ks, uint32_t* dst) {
            #pragma unroll
            for (int q = 0; q < 2; q++) {
                int r = br_base + q * 16;
                int c = 2 * ks + bc_sel;
                uint32_t addr = sb + swz(r, c);
                asm volatile("ldmatrix.sync.aligned.m8n8.x4.shared.b16 {%0,%1,%2,%3}, [%4];"
                    : "=r"(dst[q*4+0]), "=r"(dst[q*4+1]), "=r"(dst[q*4+2]), "=r"(dst[q*4+3])
                    : "r"(addr));
            }
        };
        auto ldA = [&](int ks, int mt, uint32_t* dst) {
            int r = ar_base + mt * 16;
            int c = 2 * ks + ac_sel;
            uint32_t addr = sa + swz(r, c);
            asm volatile("ldmatrix.sync.aligned.m8n8.x4.shared.b16 {%0,%1,%2,%3}, [%4];"
                : "=r"(dst[0]), "=r"(dst[1]), "=r"(dst[2]), "=r"(dst[3])
                : "r"(addr));
        };

        ldB(0, bf[0]);
        ldA(0, 0, af[0]);

        #pragma unroll
        for (int ks = 0; ks < 8; ks++) {         // 8 x k16 per BK=128
            if (ks < 7) ldB(ks + 1, bf[(ks + 1) & 1]);
            const uint32_t* b = bf[ks & 1];
            #pragma unroll
            for (int mt = 0; mt < 4; mt++) {
                if (mt < 3)      ldA(ks,     mt + 1, af[(mt + 1) & 1]);
                else if (ks < 7) ldA(ks + 1, 0,      af[0]);
                const uint32_t* a = af[mt & 1];
                #pragma unroll
                for (int nt = 0; nt < 4; nt++) {
                    asm volatile(
                        "mma.sync.aligned.m16n8k16.row.col.f32.f16.f16.f32 "
                        "{%0,%1,%2,%3},{%4,%5,%6,%7},{%8,%9},{%0,%1,%2,%3};"
                        : "+f"(acc[mt][nt][0]), "+f"(acc[mt][nt][1]),
                          "+f"(acc[mt][nt][2]), "+f"(acc[mt][nt][3])
                        : "r"(a[0]), "r"(a[1]), "r"(a[2]), "r"(a[3]),
                          "r"(b[(nt >> 1) * 4 + (nt & 1) * 2]),
                          "r"(b[(nt >> 1) * 4 + (nt & 1) * 2 + 1]));
                }
            }
        }
    };

    // 2-stage pipeline: one barrier per kt; load(kt+1) overlaps compute(kt)
    load_stage(0, 0);
    for (int kt = 0; kt < KT; kt++) {
        asm volatile("cp.async.wait_group 0;" ::: "memory");
        __syncthreads();
        if (kt + 1 < KT) load_stage(kt + 1, (kt + 1) & 1);
        compute_stage(kt & 1);
    }

    // ---- epilogue ----
    const int g   = lane >> 2;
    const int tig = lane & 3;
    #pragma unroll
    for (int mt = 0; mt < 4; mt++) {
        const int row = m0 + wm * 64 + mt * 16 + g;
        #pragma unroll
        for (int nt = 0; nt < 4; nt++) {
            const int col = n0 + wn * 32 + nt * 8 + tig * 2;
            const float b0 = __ldg(bias + col), b1 = __ldg(bias + col + 1);
            float2 v0 = make_float2(acc[mt][nt][0] + b0, acc[mt][nt][1] + b1);
            float2 v1 = make_float2(acc[mt][nt][2] + b0, acc[mt][nt][3] + b1);
            *reinterpret_cast<float2*>(y + (size_t)row       * NDIM + col) = v0;
            *reinterpret_cast<float2*>(y + (size_t)(row + 8) * NDIM + col) = v1;
        }
    }
}

// ------------------------------------------------------------------- host ----
extern "C" void kernel_launch(void* const* d_in, const int* in_sizes, int n_in,
                              void* d_out, int out_size) {
    const float* x      = (const float*)d_in[0];
    const float* values = (const float*)d_in[1];
    const int*   col    = (const int*)d_in[2];
    const float* bias   = (const float*)d_in[3];
    float* y = (float*)d_out;

    build_w_kernel<<<NDIM, 256>>>(values, col);
    cvt_x_kernel<<<8192, 256>>>((const float4*)x);

    static bool attr_set = false;
    if (!attr_set) {
        cudaFuncSetAttribute(gemm_kernel, cudaFuncAttributeMaxDynamicSharedMemorySize, SMEM_SIZE);
        attr_set = true;
    }
    gemm_kernel<<<MT * NT, 512, SMEM_SIZE>>>(bias, y);
}

// round 8
// speedup vs baseline: 1.0487x; 1.0487x over previous
#include <cuda_runtime.h>
#include <cuda_fp16.h>
#include <cstdint>

// Problem dims
#define B_ROWS 8192
#define KDIM   4096
#define NDIM   4096
#define CAPQ   492

// GEMM tiling (fp16 operands, fp32 accum) — R6 proven config
#define BM 128
#define BN 128
#define BK 64                          // 64 halves = 128 B rows
#define STAGES 3
#define MT (B_ROWS / BM)               // 64
#define NT (NDIM / BN)                 // 32
#define KT (KDIM / BK)                 // 64
#define A_BYTES (BM * BK * 2)          // 16384
#define B_BYTES (BN * BK * 2)          // 16384
#define STAGE_BYTES (A_BYTES + B_BYTES)
#define SMEM_SIZE (STAGES * STAGE_BYTES)   // 98304 (96KB) -> 2 CTAs/SM

// Scratch (allocations forbidden -> __device__ globals)
__device__ __half g_Wh[(size_t)NDIM * KDIM];   // half W, [n][k]
__device__ __half g_xh[(size_t)B_ROWS * KDIM]; // half x, [m][k]

// ------------------------------------------------------------ fused prep ----
// Blocks 0..NDIM-1: build one W row (zero smem, scatter w/ shared atomics, cvt).
// Blocks NDIM..NDIM+CVT_BLOCKS-1: convert x fp32 -> fp16, grid-stride.
// Latency-bound scatter CTAs and DRAM-bound convert CTAs co-schedule.
#define CVT_BLOCKS 2048
__global__ __launch_bounds__(256)
void prep_kernel(const float* __restrict__ values, const int* __restrict__ col,
                 const float4* __restrict__ x) {
    __shared__ float row[KDIM];
    const int tid = threadIdx.x;

    if (blockIdx.x < NDIM) {
        const int o = blockIdx.x;
        float4* r4 = (float4*)row;
        #pragma unroll
        for (int i = 0; i < KDIM / 4 / 256; i++)
            r4[i * 256 + tid] = make_float4(0.f, 0.f, 0.f, 0.f);
        __syncthreads();

        const float* v = values + (size_t)o * CAPQ;
        const int*   c = col    + (size_t)o * CAPQ;
        for (int s = tid; s < CAPQ; s += 256) {
            float val = v[s];
            if (val != 0.0f) atomicAdd(&row[c[s]], val);
        }
        __syncthreads();

        __half2* out = (__half2*)(g_Wh + (size_t)o * KDIM);
        #pragma unroll
        for (int i = 0; i < KDIM / 4 / 256; i++) {
            float4 f = r4[i * 256 + tid];
            int j = (i * 256 + tid) * 2;
            out[j]     = __floats2half2_rn(f.x, f.y);
            out[j + 1] = __floats2half2_rn(f.z, f.w);
        }
    } else {
        const size_t n4 = (size_t)B_ROWS * KDIM / 4;
        __half2* out = (__half2*)g_xh;
        for (size_t i = (size_t)(blockIdx.x - NDIM) * 256 + tid; i < n4;
             i += (size_t)CVT_BLOCKS * 256) {
            float4 v = x[i];
            out[i * 2]     = __floats2half2_rn(v.x, v.y);
            out[i * 2 + 1] = __floats2half2_rn(v.z, v.w);
        }
    }
}

// --------------------------------------------------------------- GEMM kernel -
// R6 proven version: 256 threads = 8 warps in 2(M) x 4(N); warp tile 64x32;
// mma.m16n8k16 f16->f32; 3-stage cp.async; explicit fragment double-buffering.
__global__ __launch_bounds__(256, 2)
void gemm_kernel(const float* __restrict__ bias, float* __restrict__ y)
{
    extern __shared__ __align__(128) unsigned char smem[];
    const uint32_t sbase = (uint32_t)__cvta_generic_to_shared(smem);
    const int tid  = threadIdx.x;
    const int lane = tid & 31;
    const int wid  = tid >> 5;
    const int wm   = wid & 1;      // 2 M groups of 64
    const int wn   = wid >> 1;     // 4 N groups of 32

    const int m0 = (blockIdx.x / NT) * BM;
    const int n0 = (blockIdx.x % NT) * BN;

    const __half* Ag = g_xh + (size_t)m0 * KDIM;
    const __half* Bg = g_Wh + (size_t)n0 * KDIM;

    auto load_stage = [&](int kt, int slot) {
        const uint32_t sa = sbase + slot * STAGE_BYTES;
        const uint32_t sb = sa + A_BYTES;
        const __half* ga = Ag + kt * BK;
        const __half* gb = Bg + kt * BK;
        #pragma unroll
        for (int i = 0; i < 4; i++) {
            int chunk = i * 256 + tid;
            int r = chunk >> 3, c = chunk & 7;
            uint32_t so = sa + r * 128 + ((c ^ (r & 7)) << 4);
            const __half* g = ga + (size_t)r * KDIM + c * 8;
            asm volatile("cp.async.cg.shared.global [%0], [%1], 16;" :: "r"(so), "l"(g));
        }
        #pragma unroll
        for (int i = 0; i < 4; i++) {
            int chunk = i * 256 + tid;
            int r = chunk >> 3, c = chunk & 7;
            uint32_t so = sb + r * 128 + ((c ^ (r & 7)) << 4);
            const __half* g = gb + (size_t)r * KDIM + c * 8;
            asm volatile("cp.async.cg.shared.global [%0], [%1], 16;" :: "r"(so), "l"(g));
        }
        asm volatile("cp.async.commit_group;" ::: "memory");
    };

    float acc[4][4][4];
    #pragma unroll
    for (int i = 0; i < 4; i++)
        #pragma unroll
        for (int j = 0; j < 4; j++)
            #pragma unroll
            for (int k = 0; k < 4; k++) acc[i][j][k] = 0.f;

    const int br_base = wn * 32 + ((lane >> 4) << 3) + (lane & 7);   // + q*16
    const int bc_sel  = (lane >> 3) & 1;                             // + 2*ks
    const int ar_base = wm * 64 + (lane & 15);                       // + mt*16
    const int ac_sel  = lane >> 4;                                   // + 2*ks

    auto compute_stage = [&](int slot) {
        const uint32_t sa = sbase + slot * STAGE_BYTES;
        const uint32_t sb = sa + A_BYTES;

        uint32_t bf[2][8];   // B frags, double-buffered over ks
        uint32_t af[2][4];   // A frags, double-buffered over mt

        auto ldB = [&](int ks, uint32_t* dst) {
            #pragma unroll
            for (int q = 0; q < 2; q++) {
                int r = br_base + q * 16;
                int c = 2 * ks + bc_sel;
                uint32_t addr = sb + r * 128 + ((c ^ (r & 7)) << 4);
                asm volatile("ldmatrix.sync.aligned.m8n8.x4.shared.b16 {%0,%1,%2,%3}, [%4];"
                    : "=r"(dst[q*4+0]), "=r"(dst[q*4+1]), "=r"(dst[q*4+2]), "=r"(dst[q*4+3])
                    : "r"(addr));
            }
        };
        auto ldA = [&](int ks, int mt, uint32_t* dst) {
            int r = ar_base + mt * 16;
            int c = 2 * ks + ac_sel;
            uint32_t addr = sa + r * 128 + ((c ^ (r & 7)) << 4);
            asm volatile("ldmatrix.sync.aligned.m8n8.x4.shared.b16 {%0,%1,%2,%3}, [%4];"
                : "=r"(dst[0]), "=r"(dst[1]), "=r"(dst[2]), "=r"(dst[3])
                : "r"(addr));
        };

        ldB(0, bf[0]);
        ldA(0, 0, af[0]);

        #pragma unroll
        for (int ks = 0; ks < 4; ks++) {
            if (ks < 3) ldB(ks + 1, bf[(ks + 1) & 1]);
            const uint32_t* b = bf[ks & 1];
            #pragma unroll
            for (int mt = 0; mt < 4; mt++) {
                if (mt < 3)      ldA(ks,     mt + 1, af[(mt + 1) & 1]);
                else if (ks < 3) ldA(ks + 1, 0,      af[0]);
                const uint32_t* a = af[mt & 1];
                #pragma unroll
                for (int nt = 0; nt < 4; nt++) {
                    asm volatile(
                        "mma.sync.aligned.m16n8k16.row.col.f32.f16.f16.f32 "
                        "{%0,%1,%2,%3},{%4,%5,%6,%7},{%8,%9},{%0,%1,%2,%3};"
                        : "+f"(acc[mt][nt][0]), "+f"(acc[mt][nt][1]),
                          "+f"(acc[mt][nt][2]), "+f"(acc[mt][nt][3])
                        : "r"(a[0]), "r"(a[1]), "r"(a[2]), "r"(a[3]),
                          "r"(b[(nt >> 1) * 4 + (nt & 1) * 2]),
                          "r"(b[(nt >> 1) * 4 + (nt & 1) * 2 + 1]));
                }
            }
        }
    };

    load_stage(0, 0);
    load_stage(1, 1);

    int slot = 0, nslot = 2;
    for (int kt = 0; kt < KT - 2; kt++) {
        asm volatile("cp.async.wait_group 1;" ::: "memory");
        __syncthreads();
        load_stage(kt + 2, nslot);
        compute_stage(slot);
        if (++slot == 3) slot = 0;
        if (++nslot == 3) nslot = 0;
    }
    asm volatile("cp.async.wait_group 1;" ::: "memory");
    __syncthreads();
    compute_stage(slot);
    if (++slot == 3) slot = 0;
    asm volatile("cp.async.wait_group 0;" ::: "memory");
    __syncthreads();
    compute_stage(slot);

    // ---- epilogue ----
    const int g   = lane >> 2;
    const int tig = lane & 3;
    #pragma unroll
    for (int mt = 0; mt < 4; mt++) {
        const int row = m0 + wm * 64 + mt * 16 + g;
        #pragma unroll
        for (int nt = 0; nt < 4; nt++) {
            const int col = n0 + wn * 32 + nt * 8 + tig * 2;
            const float b0 = __ldg(bias + col), b1 = __ldg(bias + col + 1);
            float2 v0 = make_float2(acc[mt][nt][0] + b0, acc[mt][nt][1] + b1);
            float2 v1 = make_float2(acc[mt][nt][2] + b0, acc[mt][nt][3] + b1);
            *reinterpret_cast<float2*>(y + (size_t)row       * NDIM + col) = v0;
            *reinterpret_cast<float2*>(y + (size_t)(row + 8) * NDIM + col) = v1;
        }
    }
}

// ------------------------------------------------------------------- host ----
extern "C" void kernel_launch(void* const* d_in, const int* in_sizes, int n_in,
                              void* d_out, int out_size) {
    const float* x      = (const float*)d_in[0];
    const float* values = (const float*)d_in[1];
    const int*   col    = (const int*)d_in[2];
    const float* bias   = (const float*)d_in[3];
    float* y = (float*)d_out;

    prep_kernel<<<NDIM + CVT_BLOCKS, 256>>>(values, col, (const float4*)x);

    static bool attr_set = false;
    if (!attr_set) {
        cudaFuncSetAttribute(gemm_kernel, cudaFuncAttributeMaxDynamicSharedMemorySize, SMEM_SIZE);
        attr_set = true;
    }
    gemm_kernel<<<MT * NT, 256, SMEM_SIZE>>>(bias, y);
}